// round 12
// baseline (speedup 1.0000x reference)
#include <cuda_runtime.h>
#include <math.h>

typedef unsigned long long u64;

#define NB 4
#define NA 256
#define GSZ 12
#define NGR 1728
#define KA 8
#define KG 32
#define NL 4
#define CODE 64
#define HID 128
#define EDGEF 64
#define NGAUSS 20
#define NATOM (NB*NA)          // 1024
#define NGRID (NB*NGR)         // 6912
#define NNODE (NATOM+NGRID)    // 7936
#define MIROWS (2*CODE+EDGEF)  // 192

#define PD_BLOCKS 256
#define PS_BLOCKS 40
#define EDGE_BLOCKS 888
#define NEDGE (NATOM*KA + NGRID*KG)   // 229376

#define NBINS 2048
#define EPB ((NEDGE + 127) / 128)     // edge-prep blocks (1792)
#define TCHUNKS 128                   // 128 chunks of 16 bins

// ---------------- static device scratch ----------------
__device__ float g_h[2][NNODE*CODE];
__device__ float g_npos[NNODE*3];
__device__ int   g_nbrA[NATOM][KA];
__device__ int   g_nbrG[NGRID][KG];
__device__ int4  g_edA[NATOM*KA];       // {nbr*64, bin*64, frac bits, 0}
__device__ int4  g_edG[NGRID*KG];
__device__ float g_Psrc[NATOM*HID];
__device__ float g_Pdst[NNODE*HID];
__device__ float g_EW1[NL][NGAUSS*HID];
__device__ float g_b1eff[NL][HID];
__device__ ulonglong2 g_T2[NL][NBINS*64];   // interleaved {row b, row b+1} pairs
__device__ float4 g_W2q[NL][32*CODE];

struct GaussC { float off[NGAUSS]; float coeff2[NGAUSS]; };

// ---------------- f32x2 helpers ----------------
__device__ __forceinline__ void ffma2(u64 &d, u64 a, u64 b) {
    asm("fma.rn.f32x2 %0, %1, %2, %0;" : "+l"(d) : "l"(a), "l"(b));
}
__device__ __forceinline__ u64 add2(u64 a, u64 b) {
    u64 r; asm("add.rn.f32x2 %0, %1, %2;" : "=l"(r) : "l"(a), "l"(b)); return r;
}
__device__ __forceinline__ u64 pk(float x, float y) {
    u64 r; asm("mov.b64 %0, {%1, %2};" : "=l"(r) : "f"(x), "f"(y)); return r;
}
__device__ __forceinline__ float2 upk(u64 v) {
    float2 r; asm("mov.b64 {%0, %1}, %2;" : "=f"(r.x), "=f"(r.y) : "l"(v)); return r;
}
__device__ __forceinline__ void barhalf(int id) {
    asm volatile("bar.sync %0, %1;" :: "r"(id), "r"(64) : "memory");
}

// ================= k_setup: init + knn_a + knn_g + weight folding =================
__global__ void __launch_bounds__(128) k_setup(
    const float* __restrict__ pos, const int* __restrict__ atype,
    const float* __restrict__ edge_W, const float* __restrict__ edge_b,
    const float* __restrict__ W1, const float* __restrict__ b1,
    const float* __restrict__ W2)
{
    __shared__ float sx[NA], sy[NA], sz[NA];
    int bid = blockIdx.x, t = threadIdx.x;

    if (bid < 248) {
        for (int i = bid * 128 + t; i < NNODE * CODE; i += 248 * 128) {
            int n = i >> 6, c = i & 63;
            g_h[0][i] = (n < NATOM && c == atype[n]) ? 1.f : 0.f;
        }
        for (int i = bid * 128 + t; i < NNODE; i += 248 * 128) {
            float x, y, z;
            if (i < NATOM) { x = pos[i*3]; y = pos[i*3+1]; z = pos[i*3+2]; }
            else {
                int g = (i - NATOM) % NGR;
                int ix = g / (GSZ*GSZ), iy = (g / GSZ) % GSZ, iz = g % GSZ;
                x = -8.25f + 1.5f*ix; y = -8.25f + 1.5f*iy; z = -8.25f + 1.5f*iz;
            }
            g_npos[i*3] = x; g_npos[i*3+1] = y; g_npos[i*3+2] = z;
        }
    } else if (bid < 248 + 256) {
        // ---- atom kNN (warp per node, stable ties) ----
        int abid = bid - 248;
        int lane = t & 31, w = t >> 5;
        int b = (abid * 4) / NA;
        for (int j = t; j < NA; j += 128) {
            int gj = b * NA + j;
            sx[j] = pos[gj*3]; sy[j] = pos[gj*3+1]; sz[j] = pos[gj*3+2];
        }
        __syncthreads();
        int il = (abid * 4 + w) % NA;
        float px = sx[il], py = sy[il], pz = sz[il];
        float d[8];
#pragma unroll
        for (int q = 0; q < 8; q++) {
            int j = q * 32 + lane;
            float dx = sx[j]-px, dy = sy[j]-py, dz = sz[j]-pz;
            float dd = dx*dx + dy*dy + dz*dz;
            d[q] = (j == il) ? 1e30f : dd;
        }
        int keep = 0;
        for (int r = 0; r < KA; r++) {
            float mv = d[0]; int mq = 0;
#pragma unroll
            for (int q = 1; q < 8; q++) if (d[q] < mv) { mv = d[q]; mq = q; }
            int mj = mq * 32 + lane;
#pragma unroll
            for (int off = 16; off; off >>= 1) {
                float ov = __shfl_xor_sync(0xffffffffu, mv, off);
                int   oj = __shfl_xor_sync(0xffffffffu, mj, off);
                if (ov < mv || (ov == mv && oj < mj)) { mv = ov; mj = oj; }
            }
            if (lane == r) keep = mj;
            if ((mj & 31) == lane) {
                int q = mj >> 5;
#pragma unroll
                for (int qq = 0; qq < 8; qq++) if (qq == q) d[qq] = 1e30f;
            }
        }
        if (lane < KA) g_nbrA[b * NA + il][lane] = b * NA + keep;
    } else if (bid < 248 + 256 + 1728) {
        // ---- grid kNN ----
        int gbid = bid - 504;
        int lane = t & 31, w = t >> 5;
        int b = (gbid * 4) / NGR;
        for (int j = t; j < NA; j += 128) {
            int gj = b * NA + j;
            sx[j] = pos[gj*3]; sy[j] = pos[gj*3+1]; sz[j] = pos[gj*3+2];
        }
        __syncthreads();
        int gl = (gbid * 4 + w) % NGR;
        int ix = gl / (GSZ*GSZ), iy = (gl / GSZ) % GSZ, iz = gl % GSZ;
        float px = -8.25f + 1.5f*ix, py = -8.25f + 1.5f*iy, pz = -8.25f + 1.5f*iz;
        float d[8];
#pragma unroll
        for (int q = 0; q < 8; q++) {
            int j = q * 32 + lane;
            float dx = sx[j]-px, dy = sy[j]-py, dz = sz[j]-pz;
            d[q] = dx*dx + dy*dy + dz*dz;
        }
        int keep = 0;
        for (int r = 0; r < KG; r++) {
            float mv = d[0]; int mq = 0;
#pragma unroll
            for (int q = 1; q < 8; q++) if (d[q] < mv) { mv = d[q]; mq = q; }
            int mj = mq * 32 + lane;
#pragma unroll
            for (int off = 16; off; off >>= 1) {
                float ov = __shfl_xor_sync(0xffffffffu, mv, off);
                int   oj = __shfl_xor_sync(0xffffffffu, mj, off);
                if (ov < mv || (ov == mv && oj < mj)) { mv = ov; mj = oj; }
            }
            if (lane == r) keep = mj;
            if ((mj & 31) == lane) {
                int q = mj >> 5;
#pragma unroll
                for (int qq = 0; qq < 8; qq++) if (qq == q) d[qq] = 1e30f;
            }
        }
        g_nbrG[b * NGR + gl][lane] = b * NA + keep;
    } else {
        // ---- weight folding ----
        int pbid = bid - 2232;
        int c = t;
        if (pbid < NL * NGAUSS) {
            int l = pbid / NGAUSS, g = pbid % NGAUSS;
            if (c < EDGEF) sx[c] = edge_W[(l * NGAUSS + g) * EDGEF + c];
            __syncthreads();
            const float* W1c = W1 + l * MIROWS * HID + 2 * CODE * HID;
            float acc = 0.f;
#pragma unroll
            for (int e = 0; e < EDGEF; e++) acc = fmaf(sx[e], W1c[e * HID + c], acc);
            g_EW1[l][g * HID + c] = acc;
        } else if (pbid < NL * NGAUSS + NL) {
            int l = pbid - NL * NGAUSS;
            if (c < EDGEF) sx[c] = edge_b[l * EDGEF + c];
            __syncthreads();
            const float* W1c = W1 + l * MIROWS * HID + 2 * CODE * HID;
            float acc = b1[l * HID + c];
#pragma unroll
            for (int e = 0; e < EDGEF; e++) acc = fmaf(sx[e], W1c[e * HID + c], acc);
            g_b1eff[l][c] = acc;
        } else {
            int l = pbid - NL * NGAUSS - NL;
            const float* W2l = W2 + l * HID * CODE;
            for (int idx = c; idx < 32 * CODE; idx += 128) {
                int k4 = idx / CODE, cc = idx % CODE;
                g_W2q[l][idx] = make_float4(W2l[(4*k4+0)*CODE + cc], W2l[(4*k4+1)*CODE + cc],
                                            W2l[(4*k4+2)*CODE + cc], W2l[(4*k4+3)*CODE + cc]);
            }
        }
    }
}

// ================= k_prep2: edge records (premultiplied) + interleaved tables =================
__global__ void __launch_bounds__(128) k_prep2(GaussC gc) {
    int bid = blockIdx.x, t = threadIdx.x;
    if (bid < EPB) {
        int tid = bid * 128 + t;
        if (tid >= NEDGE) return;
        int node, nbr;
        int4* dst;
        if (tid < NATOM * KA) {
            node = tid / KA;
            nbr = g_nbrA[node][tid % KA];
            dst = &g_edA[tid];
        } else {
            int e = tid - NATOM * KA;
            node = NATOM + e / KG;
            nbr = g_nbrG[e / KG][e % KG];
            dst = &g_edG[e];
        }
        float dx = g_npos[nbr*3]   - g_npos[node*3];
        float dy = g_npos[nbr*3+1] - g_npos[node*3+1];
        float dz = g_npos[nbr*3+2] - g_npos[node*3+2];
        float dist = fminf(sqrtf(dx*dx + dy*dy + dz*dz), 5.0f);
        float x = dist * ((float)NBINS / 5.0f);
        int bin = min((int)x, NBINS - 1);
        float fr = x - (float)bin;
        *dst = make_int4(nbr * 64, bin * 64, __float_as_int(fr), 0);
    } else {
        int tb = bid - EPB;
        int l = tb / TCHUNKS, chunk = tb % TCHUNKS;
        int b0 = chunk * 16;
        __shared__ float sg[17 * NGAUSS];
        for (int i = t; i < 17 * NGAUSS; i += 128) {
            int bb = b0 + i / NGAUSS;
            int g = i % NGAUSS;
            float d = (float)bb * (5.0f / (float)NBINS);
            float dd = d - gc.off[g];
            sg[i] = exp2f(gc.coeff2[g] * dd * dd);
        }
        __syncthreads();
        float ew[NGAUSS];
#pragma unroll
        for (int g = 0; g < NGAUSS; g++) ew[g] = g_EW1[l][g * HID + t];
        float* base = (float*)g_T2[l];
        int c = t >> 1, lohi = t & 1;
        float accPrev = 0.f;
#pragma unroll
        for (int g = 0; g < NGAUSS; g++) accPrev = fmaf(sg[g], ew[g], accPrev);
        for (int bi = 0; bi < 16; bi++) {
            float accNext = 0.f;
            const float* sgr = sg + (bi + 1) * NGAUSS;
#pragma unroll
            for (int g = 0; g < NGAUSS; g++) accNext = fmaf(sgr[g], ew[g], accNext);
            int pi = ((b0 + bi) * 64 + c) * 4 + lohi;
            base[pi]     = accPrev;
            base[pi + 2] = accNext;
            accPrev = accNext;
        }
    }
}

// ================= k_proj: Psrc (atoms) + Pdst (all), weight-stationary =================
__global__ void __launch_bounds__(128) k_proj(const float* __restrict__ W1, int l, int cur) {
    int c = threadIdx.x;
    bool srcRole = blockIdx.x >= PD_BLOCKS;
    const float* Wb = W1 + (srcRole ? 0 : CODE * HID);
    float w[CODE];
#pragma unroll
    for (int k = 0; k < CODE; k++) w[k] = Wb[k * HID + c];
    float bias = srcRole ? 0.f : g_b1eff[l][c];
    float* dst = srcRole ? g_Psrc : g_Pdst;
    int nCh = (srcRole ? NATOM : NNODE) / 4;
    int b0 = srcRole ? (blockIdx.x - PD_BLOCKS) : blockIdx.x;
    int nBlk = srcRole ? PS_BLOCKS : PD_BLOCKS;
    __shared__ __align__(16) float hsh[4 * CODE];
    const float* hsrc = g_h[cur];
    for (int ch = b0; ch < nCh; ch += nBlk) {
        int n0 = ch * 4;
        hsh[c]       = hsrc[n0 * CODE + c];
        hsh[c + 128] = hsrc[n0 * CODE + 128 + c];
        __syncthreads();
#pragma unroll
        for (int q = 0; q < 4; q++) {
            float acc = bias;
            const float4* h4 = (const float4*)(hsh + q * CODE);
#pragma unroll
            for (int k4 = 0; k4 < 16; k4++) {
                float4 hv = h4[k4];
                acc = fmaf(hv.x, w[4*k4+0], acc);
                acc = fmaf(hv.y, w[4*k4+1], acc);
                acc = fmaf(hv.z, w[4*k4+2], acc);
                acc = fmaf(hv.w, w[4*k4+3], acc);
            }
            dst[(n0 + q) * HID + c] = acc;
        }
        __syncthreads();
    }
}

// ================= k_edge: table lerp + split-K stage 2 =================
__global__ void __launch_bounds__(128, 6) k_edge(
    const float* __restrict__ b2, const float* __restrict__ lng,
    const float* __restrict__ lnb, int l, int cur, int last,
    float* __restrict__ out)
{
    __shared__ int4   sE[2][KG];
    __shared__ __align__(16) float sHS[2][HID];
    __shared__ float  sPart[2][2][CODE];   // [node][khalf][channel]
    __shared__ float2 sred[2][2];

    int t = threadIdx.x;
    int half = t >> 6, c = t & 63, lane = t & 31, hw = (t >> 5) & 1;
    int barid = 1 + half;

    float b2c = b2[c], gmc = lng[c], bbc = lnb[c];

    int nStart = last ? NATOM : 0;
    int nPairs = (NNODE - nStart) >> 1;
    const u64* psrcq = (const u64*)g_Psrc;
    const u64* pdstq = (const u64*)g_Pdst;
    const float* hcur = g_h[cur];
    const ulonglong2* w2q = (const ulonglong2*)g_W2q[l];
    const ulonglong2* T2q = g_T2[l];

    for (int p = blockIdx.x; p < nPairs; p += gridDim.x) {
        int n = nStart + 2 * p + half;
        bool atom = n < NATOM;
        int k = atom ? KA : KG;

        u64 pd = pdstq[n * 64 + c];
        float hres = __ldg(&hcur[n * CODE + c]);

        if (c < k)
            sE[half][c] = atom ? g_edA[n * KA + c] : g_edG[(n - NATOM) * KG + c];
        barhalf(barid);                       // (A) edge records ready (per half)

        float hs0 = 0.f, hs1 = 0.f;
        for (int j0 = 0; j0 < k; j0 += 4) {
            int4 e[4];
            u64 ps[4];
            ulonglong2 tt[4];
#pragma unroll
            for (int m = 0; m < 4; m++) e[m] = sE[half][j0 + m];
#pragma unroll
            for (int m = 0; m < 4; m++) {
                ps[m] = psrcq[e[m].x + c];
                tt[m] = __ldg(&T2q[e[m].y + c]);
            }
#pragma unroll
            for (int m = 0; m < 4; m++) {
                float fr = __int_as_float(e[m].z);
                float om = 1.0f - fr;
                u64 v = 0ull;
                ffma2(v, tt[m].x, pk(om, om));
                ffma2(v, tt[m].y, pk(fr, fr));
                u64 bu = add2(add2(pd, ps[m]), v);
                float2 b = upk(bu);
                hs0 += fmaxf(b.x, 0.f);
                hs1 += fmaxf(b.y, 0.f);
            }
        }
        ((float2*)sHS[half])[c] = make_float2(hs0, hs1);
        __syncthreads();                      // both halves' sHS ready

        // ---- stage 2 split-K: thread (half,c) does k4 in [16*half, 16*half+16)
        //      for BOTH nodes, reading each W2 column slice once ----
        {
            const ulonglong2* hqA = (const ulonglong2*)sHS[0];
            const ulonglong2* hqB = (const ulonglong2*)sHS[1];
            u64 aA0 = 0ull, aA1 = 0ull, aB0 = 0ull, aB1 = 0ull;
#pragma unroll
            for (int k4 = 0; k4 < 16; k4++) {
                int idx = 16 * half + k4;
                ulonglong2 wv = __ldg(&w2q[idx * CODE + c]);
                ulonglong2 hA = hqA[idx];
                ulonglong2 hB = hqB[idx];
                ffma2(aA0, hA.x, wv.x);
                ffma2(aA1, hA.y, wv.y);
                ffma2(aB0, hB.x, wv.x);
                ffma2(aB1, hB.y, wv.y);
            }
            float2 pA0 = upk(aA0), pA1 = upk(aA1);
            float2 pB0 = upk(aB0), pB1 = upk(aB1);
            sPart[0][half][c] = pA0.x + pA0.y + pA1.x + pA1.y;
            sPart[1][half][c] = pB0.x + pB0.y + pB1.x + pB1.y;
        }
        __syncthreads();                      // partials ready

        float aggr = (sPart[half][0][c] + sPart[half][1][c]) * (atom ? (1.f/KA) : (1.f/KG));
        float x = hres + aggr + b2c;

        // ---- single-pass LN (per half) ----
        float s1 = x, s2 = x * x;
#pragma unroll
        for (int off = 16; off; off >>= 1) {
            s1 += __shfl_xor_sync(0xffffffffu, s1, off);
            s2 += __shfl_xor_sync(0xffffffffu, s2, off);
        }
        if (lane == 0) sred[half][hw] = make_float2(s1, s2);
        barhalf(barid);                       // (C) sred ready
        float2 ra = sred[half][0], rb = sred[half][1];
        float mu  = (ra.x + rb.x) * (1.f / CODE);
        float var = (ra.y + rb.y) * (1.f / CODE) - mu * mu;
        float y = (x - mu) * rsqrtf(var + 1e-5f) * gmc + bbc;
        if (last) out[(n - NATOM) * CODE + c] = y;
        else      g_h[cur ^ 1][n * CODE + c] = y;
        __syncthreads();                      // protect sHS/sPart before next iter
    }
}

// ---------------- launch ----------------
extern "C" void kernel_launch(void* const* d_in, const int* in_sizes, int n_in,
                              void* d_out, int out_size) {
    const float* pos    = (const float*)d_in[0];
    const int*   atype  = (const int*)  d_in[1];
    const float* edge_W = (const float*)d_in[3];
    const float* edge_b = (const float*)d_in[4];
    const float* W1     = (const float*)d_in[5];
    const float* b1     = (const float*)d_in[6];
    const float* W2     = (const float*)d_in[7];
    const float* b2     = (const float*)d_in[8];
    const float* lng    = (const float*)d_in[9];
    const float* lnb    = (const float*)d_in[10];
    float* out = (float*)d_out;

    GaussC gc;
    {
        double off[NGAUSS], dd[NGAUSS];
        double hi = log(6.0);
        for (int g = 0; g < NGAUSS; g++) off[g] = exp(hi * (double)g / 19.0) - 1.0;
        for (int g = NGAUSS - 1; g >= 1; g--) dd[g] = off[g] - off[g-1];
        dd[0] = dd[1];
        for (int g = 0; g < NGAUSS; g++) {
            double coeff = -0.5 / (dd[g] * dd[g]);
            gc.off[g]    = (float)off[g];
            gc.coeff2[g] = (float)(coeff * 1.4426950408889634);
        }
    }

    k_setup<<<2232 + NL*NGAUSS + 2*NL, 128>>>(pos, atype, edge_W, edge_b, W1, b1, W2);
    k_prep2<<<EPB + NL*TCHUNKS, 128>>>(gc);

    int cur = 0;
    for (int l = 0; l < NL; l++) {
        int last = (l == NL - 1) ? 1 : 0;
        k_proj<<<PD_BLOCKS + PS_BLOCKS, 128>>>(W1 + l*MIROWS*HID, l, cur);
        k_edge<<<EDGE_BLOCKS, 128>>>(b2 + l*CODE, lng + l*CODE, lnb + l*CODE,
                                     l, cur, last, out);
        cur ^= 1;
    }
}

// round 13
// speedup vs baseline: 1.2238x; 1.2238x over previous
#include <cuda_runtime.h>
#include <math.h>

typedef unsigned long long u64;

#define NB 4
#define NA 256
#define GSZ 12
#define NGR 1728
#define KA 8
#define KG 32
#define NL 4
#define CODE 64
#define HID 128
#define EDGEF 64
#define NGAUSS 20
#define NATOM (NB*NA)          // 1024
#define NGRID (NB*NGR)         // 6912
#define NNODE (NATOM+NGRID)    // 7936
#define MIROWS (2*CODE+EDGEF)  // 192

#define PD_BLOCKS 256
#define PS_BLOCKS 40
#define EDGE_BLOCKS 888
#define NEDGE (NATOM*KA + NGRID*KG)   // 229376

#define NBINS 2048
#define EPB ((NEDGE + 127) / 128)     // edge-prep blocks (1792)
#define TCHUNKS 128                   // 128 chunks of 16 bins

// ---------------- static device scratch ----------------
__device__ float g_h[2][NNODE*CODE];
__device__ float g_npos[NNODE*3];
__device__ int   g_nbrA[NATOM][KA];
__device__ int   g_nbrG[NGRID][KG];
__device__ int4  g_edA[NATOM*KA];       // {nbr*64, bin*64, frac bits, 0}
__device__ int4  g_edG[NGRID*KG];
__device__ float g_Psrc[NATOM*HID];
__device__ float g_Pdst[NNODE*HID];
__device__ float g_EW1[NL][NGAUSS*HID];
__device__ float g_b1eff[NL][HID];
__device__ ulonglong2 g_T2[NL][NBINS*64];   // interleaved {row b, row b+1} pairs
__device__ float4 g_W2q[NL][32*CODE];

struct GaussC { float off[NGAUSS]; float coeff2[NGAUSS]; };

// ---------------- f32x2 helpers ----------------
__device__ __forceinline__ void ffma2(u64 &d, u64 a, u64 b) {
    asm("fma.rn.f32x2 %0, %1, %2, %0;" : "+l"(d) : "l"(a), "l"(b));
}
__device__ __forceinline__ u64 add2(u64 a, u64 b) {
    u64 r; asm("add.rn.f32x2 %0, %1, %2;" : "=l"(r) : "l"(a), "l"(b)); return r;
}
__device__ __forceinline__ u64 pk(float x, float y) {
    u64 r; asm("mov.b64 %0, {%1, %2};" : "=l"(r) : "f"(x), "f"(y)); return r;
}
__device__ __forceinline__ float2 upk(u64 v) {
    float2 r; asm("mov.b64 {%0, %1}, %2;" : "=f"(r.x), "=f"(r.y) : "l"(v)); return r;
}
__device__ __forceinline__ void barhalf(int id) {
    asm volatile("bar.sync %0, %1;" :: "r"(id), "r"(64) : "memory");
}

// ================= k_setup: init + knn_a + knn_g + weight folding =================
__global__ void __launch_bounds__(128) k_setup(
    const float* __restrict__ pos, const int* __restrict__ atype,
    const float* __restrict__ edge_W, const float* __restrict__ edge_b,
    const float* __restrict__ W1, const float* __restrict__ b1,
    const float* __restrict__ W2)
{
    __shared__ float sx[NA], sy[NA], sz[NA];
    int bid = blockIdx.x, t = threadIdx.x;

    if (bid < 248) {
        for (int i = bid * 128 + t; i < NNODE * CODE; i += 248 * 128) {
            int n = i >> 6, c = i & 63;
            g_h[0][i] = (n < NATOM && c == atype[n]) ? 1.f : 0.f;
        }
        for (int i = bid * 128 + t; i < NNODE; i += 248 * 128) {
            float x, y, z;
            if (i < NATOM) { x = pos[i*3]; y = pos[i*3+1]; z = pos[i*3+2]; }
            else {
                int g = (i - NATOM) % NGR;
                int ix = g / (GSZ*GSZ), iy = (g / GSZ) % GSZ, iz = g % GSZ;
                x = -8.25f + 1.5f*ix; y = -8.25f + 1.5f*iy; z = -8.25f + 1.5f*iz;
            }
            g_npos[i*3] = x; g_npos[i*3+1] = y; g_npos[i*3+2] = z;
        }
    } else if (bid < 248 + 256) {
        // ---- atom kNN (warp per node, stable ties) ----
        int abid = bid - 248;
        int lane = t & 31, w = t >> 5;
        int b = (abid * 4) / NA;
        for (int j = t; j < NA; j += 128) {
            int gj = b * NA + j;
            sx[j] = pos[gj*3]; sy[j] = pos[gj*3+1]; sz[j] = pos[gj*3+2];
        }
        __syncthreads();
        int il = (abid * 4 + w) % NA;
        float px = sx[il], py = sy[il], pz = sz[il];
        float d[8];
#pragma unroll
        for (int q = 0; q < 8; q++) {
            int j = q * 32 + lane;
            float dx = sx[j]-px, dy = sy[j]-py, dz = sz[j]-pz;
            float dd = dx*dx + dy*dy + dz*dz;
            d[q] = (j == il) ? 1e30f : dd;
        }
        int keep = 0;
        for (int r = 0; r < KA; r++) {
            float mv = d[0]; int mq = 0;
#pragma unroll
            for (int q = 1; q < 8; q++) if (d[q] < mv) { mv = d[q]; mq = q; }
            int mj = mq * 32 + lane;
#pragma unroll
            for (int off = 16; off; off >>= 1) {
                float ov = __shfl_xor_sync(0xffffffffu, mv, off);
                int   oj = __shfl_xor_sync(0xffffffffu, mj, off);
                if (ov < mv || (ov == mv && oj < mj)) { mv = ov; mj = oj; }
            }
            if (lane == r) keep = mj;
            if ((mj & 31) == lane) {
                int q = mj >> 5;
#pragma unroll
                for (int qq = 0; qq < 8; qq++) if (qq == q) d[qq] = 1e30f;
            }
        }
        if (lane < KA) g_nbrA[b * NA + il][lane] = b * NA + keep;
    } else if (bid < 248 + 256 + 1728) {
        // ---- grid kNN ----
        int gbid = bid - 504;
        int lane = t & 31, w = t >> 5;
        int b = (gbid * 4) / NGR;
        for (int j = t; j < NA; j += 128) {
            int gj = b * NA + j;
            sx[j] = pos[gj*3]; sy[j] = pos[gj*3+1]; sz[j] = pos[gj*3+2];
        }
        __syncthreads();
        int gl = (gbid * 4 + w) % NGR;
        int ix = gl / (GSZ*GSZ), iy = (gl / GSZ) % GSZ, iz = gl % GSZ;
        float px = -8.25f + 1.5f*ix, py = -8.25f + 1.5f*iy, pz = -8.25f + 1.5f*iz;
        float d[8];
#pragma unroll
        for (int q = 0; q < 8; q++) {
            int j = q * 32 + lane;
            float dx = sx[j]-px, dy = sy[j]-py, dz = sz[j]-pz;
            d[q] = dx*dx + dy*dy + dz*dz;
        }
        int keep = 0;
        for (int r = 0; r < KG; r++) {
            float mv = d[0]; int mq = 0;
#pragma unroll
            for (int q = 1; q < 8; q++) if (d[q] < mv) { mv = d[q]; mq = q; }
            int mj = mq * 32 + lane;
#pragma unroll
            for (int off = 16; off; off >>= 1) {
                float ov = __shfl_xor_sync(0xffffffffu, mv, off);
                int   oj = __shfl_xor_sync(0xffffffffu, mj, off);
                if (ov < mv || (ov == mv && oj < mj)) { mv = ov; mj = oj; }
            }
            if (lane == r) keep = mj;
            if ((mj & 31) == lane) {
                int q = mj >> 5;
#pragma unroll
                for (int qq = 0; qq < 8; qq++) if (qq == q) d[qq] = 1e30f;
            }
        }
        g_nbrG[b * NGR + gl][lane] = b * NA + keep;
    } else {
        // ---- weight folding ----
        int pbid = bid - 2232;
        int c = t;
        if (pbid < NL * NGAUSS) {
            int l = pbid / NGAUSS, g = pbid % NGAUSS;
            if (c < EDGEF) sx[c] = edge_W[(l * NGAUSS + g) * EDGEF + c];
            __syncthreads();
            const float* W1c = W1 + l * MIROWS * HID + 2 * CODE * HID;
            float acc = 0.f;
#pragma unroll
            for (int e = 0; e < EDGEF; e++) acc = fmaf(sx[e], W1c[e * HID + c], acc);
            g_EW1[l][g * HID + c] = acc;
        } else if (pbid < NL * NGAUSS + NL) {
            int l = pbid - NL * NGAUSS;
            if (c < EDGEF) sx[c] = edge_b[l * EDGEF + c];
            __syncthreads();
            const float* W1c = W1 + l * MIROWS * HID + 2 * CODE * HID;
            float acc = b1[l * HID + c];
#pragma unroll
            for (int e = 0; e < EDGEF; e++) acc = fmaf(sx[e], W1c[e * HID + c], acc);
            g_b1eff[l][c] = acc;
        } else {
            int l = pbid - NL * NGAUSS - NL;
            const float* W2l = W2 + l * HID * CODE;
            for (int idx = c; idx < 32 * CODE; idx += 128) {
                int k4 = idx / CODE, cc = idx % CODE;
                g_W2q[l][idx] = make_float4(W2l[(4*k4+0)*CODE + cc], W2l[(4*k4+1)*CODE + cc],
                                            W2l[(4*k4+2)*CODE + cc], W2l[(4*k4+3)*CODE + cc]);
            }
        }
    }
}

// ================= k_prep2: edge records (premultiplied) + interleaved tables =================
__global__ void __launch_bounds__(128) k_prep2(GaussC gc) {
    int bid = blockIdx.x, t = threadIdx.x;
    if (bid < EPB) {
        int tid = bid * 128 + t;
        if (tid >= NEDGE) return;
        int node, nbr;
        int4* dst;
        if (tid < NATOM * KA) {
            node = tid / KA;
            nbr = g_nbrA[node][tid % KA];
            dst = &g_edA[tid];
        } else {
            int e = tid - NATOM * KA;
            node = NATOM + e / KG;
            nbr = g_nbrG[e / KG][e % KG];
            dst = &g_edG[e];
        }
        float dx = g_npos[nbr*3]   - g_npos[node*3];
        float dy = g_npos[nbr*3+1] - g_npos[node*3+1];
        float dz = g_npos[nbr*3+2] - g_npos[node*3+2];
        float dist = fminf(sqrtf(dx*dx + dy*dy + dz*dz), 5.0f);
        float x = dist * ((float)NBINS / 5.0f);
        int bin = min((int)x, NBINS - 1);
        float fr = x - (float)bin;
        *dst = make_int4(nbr * 64, bin * 64, __float_as_int(fr), 0);
    } else {
        int tb = bid - EPB;
        int l = tb / TCHUNKS, chunk = tb % TCHUNKS;
        int b0 = chunk * 16;
        __shared__ float sg[17 * NGAUSS];
        for (int i = t; i < 17 * NGAUSS; i += 128) {
            int bb = b0 + i / NGAUSS;
            int g = i % NGAUSS;
            float d = (float)bb * (5.0f / (float)NBINS);
            float dd = d - gc.off[g];
            sg[i] = exp2f(gc.coeff2[g] * dd * dd);
        }
        __syncthreads();
        float ew[NGAUSS];
#pragma unroll
        for (int g = 0; g < NGAUSS; g++) ew[g] = g_EW1[l][g * HID + t];
        float* base = (float*)g_T2[l];
        int c = t >> 1, lohi = t & 1;
        float accPrev = 0.f;
#pragma unroll
        for (int g = 0; g < NGAUSS; g++) accPrev = fmaf(sg[g], ew[g], accPrev);
        for (int bi = 0; bi < 16; bi++) {
            float accNext = 0.f;
            const float* sgr = sg + (bi + 1) * NGAUSS;
#pragma unroll
            for (int g = 0; g < NGAUSS; g++) accNext = fmaf(sgr[g], ew[g], accNext);
            int pi = ((b0 + bi) * 64 + c) * 4 + lohi;
            base[pi]     = accPrev;
            base[pi + 2] = accNext;
            accPrev = accNext;
        }
    }
}

// ================= k_proj: Psrc (atoms) + Pdst (all), weight-stationary =================
__global__ void __launch_bounds__(128) k_proj(const float* __restrict__ W1, int l, int cur) {
    int c = threadIdx.x;
    bool srcRole = blockIdx.x >= PD_BLOCKS;
    const float* Wb = W1 + (srcRole ? 0 : CODE * HID);
    float w[CODE];
#pragma unroll
    for (int k = 0; k < CODE; k++) w[k] = Wb[k * HID + c];
    float bias = srcRole ? 0.f : g_b1eff[l][c];
    float* dst = srcRole ? g_Psrc : g_Pdst;
    int nCh = (srcRole ? NATOM : NNODE) / 4;
    int b0 = srcRole ? (blockIdx.x - PD_BLOCKS) : blockIdx.x;
    int nBlk = srcRole ? PS_BLOCKS : PD_BLOCKS;
    __shared__ __align__(16) float hsh[4 * CODE];
    const float* hsrc = g_h[cur];
    for (int ch = b0; ch < nCh; ch += nBlk) {
        int n0 = ch * 4;
        hsh[c]       = hsrc[n0 * CODE + c];
        hsh[c + 128] = hsrc[n0 * CODE + 128 + c];
        __syncthreads();
#pragma unroll
        for (int q = 0; q < 4; q++) {
            float acc = bias;
            const float4* h4 = (const float4*)(hsh + q * CODE);
#pragma unroll
            for (int k4 = 0; k4 < 16; k4++) {
                float4 hv = h4[k4];
                acc = fmaf(hv.x, w[4*k4+0], acc);
                acc = fmaf(hv.y, w[4*k4+1], acc);
                acc = fmaf(hv.z, w[4*k4+2], acc);
                acc = fmaf(hv.w, w[4*k4+3], acc);
            }
            dst[(n0 + q) * HID + c] = acc;
        }
        __syncthreads();
    }
}

// ================= k_edge: 2 nodes per half (quad per block iter), table lerp =================
__global__ void __launch_bounds__(128, 5) k_edge(
    const float* __restrict__ b2, const float* __restrict__ lng,
    const float* __restrict__ lnb, int l, int cur, int last,
    float* __restrict__ out)
{
    __shared__ int4   sE[2][2][KG];
    __shared__ __align__(16) float sHS[2][2][HID];
    __shared__ float2 sred[2][2][2];   // [half][sub][warp-half]

    int t = threadIdx.x;
    int half = t >> 6, c = t & 63, lane = t & 31, hw = (t >> 5) & 1;
    int barid = 1 + half;

    float b2c = b2[c], gmc = lng[c], bbc = lnb[c];

    int nStart = last ? NATOM : 0;
    int nQuads = (NNODE - nStart) >> 2;
    const u64* psrcq = (const u64*)g_Psrc;
    const u64* pdstq = (const u64*)g_Pdst;
    const float* hcur = g_h[cur];
    const ulonglong2* w2q = (const ulonglong2*)g_W2q[l];
    const ulonglong2* T2q = g_T2[l];

    for (int p = blockIdx.x; p < nQuads; p += gridDim.x) {
        int nA = nStart + 4 * p + 2 * half;
        int nB = nA + 1;
        bool atom = nA < NATOM;      // quad is type-uniform
        int k = atom ? KA : KG;

        u64 pdA = pdstq[nA * 64 + c];
        u64 pdB = pdstq[nB * 64 + c];
        float hresA = __ldg(&hcur[nA * CODE + c]);
        float hresB = __ldg(&hcur[nB * CODE + c]);

        if (c < k) {
            if (atom) {
                sE[half][0][c] = g_edA[nA * KA + c];
                sE[half][1][c] = g_edA[nB * KA + c];
            } else {
                sE[half][0][c] = g_edG[(nA - NATOM) * KG + c];
                sE[half][1][c] = g_edG[(nB - NATOM) * KG + c];
            }
        }
        barhalf(barid);                       // (A) edge records ready

        float hsA0 = 0.f, hsA1 = 0.f, hsB0 = 0.f, hsB1 = 0.f;
        for (int j0 = 0; j0 < k; j0 += 4) {
            int4 eA[4], eB[4];
            u64 psA[4], psB[4];
            ulonglong2 ttA[4], ttB[4];
#pragma unroll
            for (int m = 0; m < 4; m++) { eA[m] = sE[half][0][j0 + m]; eB[m] = sE[half][1][j0 + m]; }
#pragma unroll
            for (int m = 0; m < 4; m++) {
                psA[m] = psrcq[eA[m].x + c];
                ttA[m] = __ldg(&T2q[eA[m].y + c]);
            }
#pragma unroll
            for (int m = 0; m < 4; m++) {
                psB[m] = psrcq[eB[m].x + c];
                ttB[m] = __ldg(&T2q[eB[m].y + c]);
            }
#pragma unroll
            for (int m = 0; m < 4; m++) {
                float fr = __int_as_float(eA[m].z);
                float om = 1.0f - fr;
                u64 v = 0ull;
                ffma2(v, ttA[m].x, pk(om, om));
                ffma2(v, ttA[m].y, pk(fr, fr));
                float2 b = upk(add2(add2(pdA, psA[m]), v));
                hsA0 += fmaxf(b.x, 0.f);
                hsA1 += fmaxf(b.y, 0.f);
            }
#pragma unroll
            for (int m = 0; m < 4; m++) {
                float fr = __int_as_float(eB[m].z);
                float om = 1.0f - fr;
                u64 v = 0ull;
                ffma2(v, ttB[m].x, pk(om, om));
                ffma2(v, ttB[m].y, pk(fr, fr));
                float2 b = upk(add2(add2(pdB, psB[m]), v));
                hsB0 += fmaxf(b.x, 0.f);
                hsB1 += fmaxf(b.y, 0.f);
            }
        }
        ((float2*)sHS[half][0])[c] = make_float2(hsA0, hsA1);
        ((float2*)sHS[half][1])[c] = make_float2(hsB0, hsB1);
        barhalf(barid);                       // (B) sHS ready

        // ---- stage 2: W2 read once serves BOTH nodes of this half ----
        u64 aA0 = 0ull, aA1 = 0ull, aB0 = 0ull, aB1 = 0ull;
        const ulonglong2* hqA = (const ulonglong2*)sHS[half][0];
        const ulonglong2* hqB = (const ulonglong2*)sHS[half][1];
#pragma unroll 8
        for (int k4 = 0; k4 < 32; k4++) {
            ulonglong2 wv = __ldg(&w2q[k4 * CODE + c]);
            ulonglong2 hA = hqA[k4];
            ulonglong2 hB = hqB[k4];
            ffma2(aA0, hA.x, wv.x);
            ffma2(aA1, hA.y, wv.y);
            ffma2(aB0, hB.x, wv.x);
            ffma2(aB1, hB.y, wv.y);
        }
        float inv = atom ? (1.f / KA) : (1.f / KG);
        float2 pA0 = upk(aA0), pA1 = upk(aA1);
        float2 pB0 = upk(aB0), pB1 = upk(aB1);
        float xA = hresA + (pA0.x + pA0.y + pA1.x + pA1.y) * inv + b2c;
        float xB = hresB + (pB0.x + pB0.y + pB1.x + pB1.y) * inv + b2c;

        // ---- single-pass LN for both nodes (combined shuffles) ----
        float sA1 = xA, sA2 = xA * xA, sB1 = xB, sB2 = xB * xB;
#pragma unroll
        for (int off = 16; off; off >>= 1) {
            sA1 += __shfl_xor_sync(0xffffffffu, sA1, off);
            sA2 += __shfl_xor_sync(0xffffffffu, sA2, off);
            sB1 += __shfl_xor_sync(0xffffffffu, sB1, off);
            sB2 += __shfl_xor_sync(0xffffffffu, sB2, off);
        }
        if (lane == 0) {
            sred[half][0][hw] = make_float2(sA1, sA2);
            sred[half][1][hw] = make_float2(sB1, sB2);
        }
        barhalf(barid);                       // (C) sred ready
        {
            float2 ra = sred[half][0][0], rb = sred[half][0][1];
            float mu  = (ra.x + rb.x) * (1.f / CODE);
            float var = (ra.y + rb.y) * (1.f / CODE) - mu * mu;
            float y = (xA - mu) * rsqrtf(var + 1e-5f) * gmc + bbc;
            if (last) out[(nA - NATOM) * CODE + c] = y;
            else      g_h[cur ^ 1][nA * CODE + c] = y;
        }
        {
            float2 ra = sred[half][1][0], rb = sred[half][1][1];
            float mu  = (ra.x + rb.x) * (1.f / CODE);
            float var = (ra.y + rb.y) * (1.f / CODE) - mu * mu;
            float y = (xB - mu) * rsqrtf(var + 1e-5f) * gmc + bbc;
            if (last) out[(nB - NATOM) * CODE + c] = y;
            else      g_h[cur ^ 1][nB * CODE + c] = y;
        }
    }
}

// ---------------- launch ----------------
extern "C" void kernel_launch(void* const* d_in, const int* in_sizes, int n_in,
                              void* d_out, int out_size) {
    const float* pos    = (const float*)d_in[0];
    const int*   atype  = (const int*)  d_in[1];
    const float* edge_W = (const float*)d_in[3];
    const float* edge_b = (const float*)d_in[4];
    const float* W1     = (const float*)d_in[5];
    const float* b1     = (const float*)d_in[6];
    const float* W2     = (const float*)d_in[7];
    const float* b2     = (const float*)d_in[8];
    const float* lng    = (const float*)d_in[9];
    const float* lnb    = (const float*)d_in[10];
    float* out = (float*)d_out;

    GaussC gc;
    {
        double off[NGAUSS], dd[NGAUSS];
        double hi = log(6.0);
        for (int g = 0; g < NGAUSS; g++) off[g] = exp(hi * (double)g / 19.0) - 1.0;
        for (int g = NGAUSS - 1; g >= 1; g--) dd[g] = off[g] - off[g-1];
        dd[0] = dd[1];
        for (int g = 0; g < NGAUSS; g++) {
            double coeff = -0.5 / (dd[g] * dd[g]);
            gc.off[g]    = (float)off[g];
            gc.coeff2[g] = (float)(coeff * 1.4426950408889634);
        }
    }

    k_setup<<<2232 + NL*NGAUSS + 2*NL, 128>>>(pos, atype, edge_W, edge_b, W1, b1, W2);
    k_prep2<<<EPB + NL*TCHUNKS, 128>>>(gc);

    int cur = 0;
    for (int l = 0; l < NL; l++) {
        int last = (l == NL - 1) ? 1 : 0;
        k_proj<<<PD_BLOCKS + PS_BLOCKS, 128>>>(W1 + l*MIROWS*HID, l, cur);
        k_edge<<<EDGE_BLOCKS, 128>>>(b2 + l*CODE, lng + l*CODE, lnb + l*CODE,
                                     l, cur, last, out);
        cur ^= 1;
    }
}